// round 8
// baseline (speedup 1.0000x reference)
#include <cuda_runtime.h>
#include <cstdint>

// FactorGNN fused pipeline (dead attention branch removed).
//   A = supports, A[j,j] = (diag==0 ? 1 : diag)
//   deg[j] = sum_i A[i,j];  dinv = deg>0 ? rsqrt(deg) : 0
//   M[i,c] = dinv[i] * (x[b,i,:] @ W_gcn)      c = b*16+o  (64 cols)
//   C[j,c] = sum_i supports[i,j] * M[i,c]      (register-streamed GEMM, split-K=4)
//   g      = relu(dinv[j]*(C + corr[j]*M[j,c]) + b_gcn)
//   out    = g.reshape(.,160) @ W_out + b_out

#define NF     10240
#define NB     4
#define NN     1024
#define FF     10
#define DD     16
#define DOUTC  16
#define NCOL   64
#define ROWCH  40
#define KSPLIT 4
#define KCHUNK 2560          // 4*2560 = 10240, 80 stages of 32
#define NST    (KCHUNK/32)   // 80

// Scratch (static device globals: allocation-free per harness rules)
__device__ float g_M[NF * NCOL];
__device__ float g_C[KSPLIT][NF * NCOL];
__device__ float g_degpart[ROWCH * NF];
__device__ float g_dinv[NF];
__device__ float g_corr[NF];

// ---- packed f32x2 helpers (sm_103a FFMA2 path) ----
__device__ __forceinline__ unsigned long long pk2(float lo, float hi) {
    unsigned long long r;
    asm("mov.b64 %0, {%1, %2};" : "=l"(r) : "f"(lo), "f"(hi));
    return r;
}
__device__ __forceinline__ void fma2(unsigned long long& d,
                                     unsigned long long a, unsigned long long b) {
    asm("fma.rn.f32x2 %0, %1, %2, %0;" : "+l"(d) : "l"(a), "l"(b));
}
__device__ __forceinline__ float2 upk2(unsigned long long v) {
    float2 f;
    asm("mov.b64 {%0, %1}, %2;" : "=f"(f.x), "=f"(f.y) : "l"(v));
    return f;
}

// ---- cp.async helpers ----
__device__ __forceinline__ void cpasync16(uint32_t saddr, const void* gptr) {
    asm volatile("cp.async.cg.shared.global [%0], [%1], 16;"
                 :: "r"(saddr), "l"(gptr));
}
__device__ __forceinline__ void cpasync_commit() {
    asm volatile("cp.async.commit_group;");
}
template <int N>
__device__ __forceinline__ void cpasync_wait() {
    asm volatile("cp.async.wait_group %0;" :: "n"(N));
}

// K1: partial column sums of supports (float4 lanes, HBM-bound)
__global__ void k_degpart(const float* __restrict__ S) {
    int j4 = blockIdx.x * 256 + threadIdx.x;       // float4 column group
    int r0 = blockIdx.y * 256;
    const float4* p = (const float4*)S + (size_t)r0 * (NF / 4) + j4;
    float4 s = make_float4(0.f, 0.f, 0.f, 0.f);
#pragma unroll 8
    for (int r = 0; r < 256; r++) {
        float4 v = __ldcs(p + (size_t)r * (NF / 4));
        s.x += v.x; s.y += v.y; s.z += v.z; s.w += v.w;
    }
    ((float4*)g_degpart)[(size_t)blockIdx.y * (NF / 4) + j4] = s;
}

// K2: reduce partials, self-loop fix, produce dinv & corr
__global__ void k_finalize(const float* __restrict__ S) {
    int j = blockIdx.x * 256 + threadIdx.x;
    float s = 0.f;
#pragma unroll
    for (int p = 0; p < ROWCH; p++) s += g_degpart[p * NF + j];
    float diag = S[(size_t)j * NF + j];
    float corr = (diag == 0.f) ? 1.f : 0.f;
    float deg  = s + corr;
    g_dinv[j] = (deg > 0.f) ? rsqrtf(deg) : 0.f;
    g_corr[j] = corr;
}

// K3: M = dinv[i] * (x @ W_gcn), layout g_M[i*64 + b*16 + o]
__global__ void k_hs(const float* __restrict__ x, const float* __restrict__ Wg) {
    __shared__ float sW[DD * DOUTC];
    if (threadIdx.x < DD * DOUTC) sW[threadIdx.x] = Wg[threadIdx.x];
    __syncthreads();
    int g = blockIdx.x * 256 + threadIdx.x;
    int o = g & 15;
    int rest = g >> 4;
    int i = rest % NF;
    int b = rest / NF;
    const float* xr = x + ((size_t)b * NF + i) * DD;
    float h = 0.f;
#pragma unroll
    for (int d = 0; d < DD; d++) h = fmaf(xr[d], sW[d * DOUTC + o], h);
    g_M[i * NCOL + b * DOUTC + o] = g_dinv[i] * h;
}

// K4: C[ks][j,c] = sum_i S[i,j]*M[i,c].
// 256 thr = 8 warps. Warp w = c-group (c0 = w*8, warp-uniform -> broadcast LDS).
// lane jt = tx&31 -> 4 j per thread (one LDG.128 from S per row).
// S: depth-8 register ring (latency 577 fully covered).
// M: smem 32-row stages, double-buffered via cp.async.
__global__ __launch_bounds__(256, 2) void k_gemm(const float* __restrict__ S) {
    __shared__ alignas(16) float sM[2][32 * NCOL];

    const int tx = threadIdx.x;
    const int cg = tx >> 5;                 // 0..7, uniform within warp
    const int jt = tx & 31;                 // 0..31
    const int j  = blockIdx.x * 128 + jt * 4;
    const int c0 = cg * 8;
    const int ks = blockIdx.y;
    const int i0 = ks * KCHUNK;

    unsigned long long acc[4][4];
#pragma unroll
    for (int q = 0; q < 4; q++)
#pragma unroll
        for (int p = 0; p < 4; p++) acc[q][p] = 0ull;

    // S depth-8 register ring: rows i0..i0+7 preloaded
    const float4* Sbase = (const float4*)S + (j >> 2);
    float4 rs[8];
#pragma unroll
    for (int d = 0; d < 8; d++)
        rs[d] = Sbase[(size_t)(i0 + d) * (NF / 4)];
    const float4* Spf = Sbase + (size_t)(i0 + 8) * (NF / 4);

    const float4* Mg = (const float4*)g_M;
    // prologue: stage 0 -> buf 0
    {
        uint32_t sa = (uint32_t)__cvta_generic_to_shared(&sM[0][0]);
        const float4* src = Mg + (size_t)i0 * (NCOL / 4);
        cpasync16(sa + tx * 16, src + tx);
        cpasync16(sa + (tx + 256) * 16, src + tx + 256);
        cpasync_commit();
    }

    for (int t = 0; t < NST; ++t) {
        const int buf = t & 1;
        if (t + 1 < NST) {
            uint32_t sa = (uint32_t)__cvta_generic_to_shared(&sM[buf ^ 1][0]);
            const float4* src = Mg + (size_t)(i0 + (t + 1) * 32) * (NCOL / 4);
            cpasync16(sa + tx * 16, src + tx);
            cpasync16(sa + (tx + 256) * 16, src + tx + 256);
            cpasync_commit();
            cpasync_wait<1>();                // stage t landed
        } else {
            cpasync_wait<0>();
        }
        __syncthreads();

        const int sb = i0 + t * 32;
#pragma unroll 8
        for (int k = 0; k < 32; ++k) {
            const int i = sb + k;
            float4 sv = rs[k & 7];
            rs[k & 7] = *Spf;                  // prefetch row i+8 (clamped)
            Spf += ((i + 9) < NF) ? (NF / 4) : 0;

            const float* mr = &sM[buf][k * NCOL + c0];
            ulonglong2 mA = *(const ulonglong2*)(mr);       // broadcast LDS.128
            ulonglong2 mB = *(const ulonglong2*)(mr + 4);
            unsigned long long b0 = mA.x, b1 = mA.y, b2 = mB.x, b3 = mB.y;

            unsigned long long a;
            a = pk2(sv.x, sv.x);
            fma2(acc[0][0], a, b0); fma2(acc[0][1], a, b1);
            fma2(acc[0][2], a, b2); fma2(acc[0][3], a, b3);
            a = pk2(sv.y, sv.y);
            fma2(acc[1][0], a, b0); fma2(acc[1][1], a, b1);
            fma2(acc[1][2], a, b2); fma2(acc[1][3], a, b3);
            a = pk2(sv.z, sv.z);
            fma2(acc[2][0], a, b0); fma2(acc[2][1], a, b1);
            fma2(acc[2][2], a, b2); fma2(acc[2][3], a, b3);
            a = pk2(sv.w, sv.w);
            fma2(acc[3][0], a, b0); fma2(acc[3][1], a, b1);
            fma2(acc[3][2], a, b2); fma2(acc[3][3], a, b3);
        }
        __syncthreads();                       // protect buf before overwrite
    }

    // write partials: rows j..j+3, cols c0..c0+7
#pragma unroll
    for (int q = 0; q < 4; q++) {
        float* Cp = g_C[ks] + (size_t)(j + q) * NCOL + c0;
        float2 v0 = upk2(acc[q][0]), v1 = upk2(acc[q][1]);
        float2 v2 = upk2(acc[q][2]), v3 = upk2(acc[q][3]);
        *(float4*)(Cp + 0) = make_float4(v0.x, v0.y, v1.x, v1.y);
        *(float4*)(Cp + 4) = make_float4(v2.x, v2.y, v3.x, v3.y);
    }
}

// K5: epilogue (sum split-K, diag corr, dinv[j], bias, relu) + output GEMM 160x16
__global__ void k_out(const float* __restrict__ Wout, const float* __restrict__ bgcn,
                      const float* __restrict__ bout, float* __restrict__ out) {
    __shared__ float sW[FF * DOUTC * DOUTC];
    __shared__ float sg[8][FF * DOUTC];
    __shared__ float sbg[DOUTC], sbo[DOUTC];
    const int tx = threadIdx.x;
    for (int i = tx; i < FF * DOUTC * DOUTC; i += 128) sW[i] = Wout[i];
    if (tx < DOUTC) { sbg[tx] = bgcn[tx]; sbo[tx] = bout[tx]; }
    __syncthreads();

    const int r = tx >> 4, o = tx & 15;
    const int gr = blockIdx.x * 8 + r;          // (b,n) flat, 0..4095
    const int b = gr >> 10, n = gr & 1023;

#pragma unroll
    for (int f = 0; f < FF; f++) {
        const int j = n * FF + f;
        const int cidx = j * NCOL + b * DOUTC + o;
        float v = 0.f;
#pragma unroll
        for (int s = 0; s < KSPLIT; s++) v += g_C[s][cidx];
        v += g_corr[j] * g_M[cidx];
        v = g_dinv[j] * v + sbg[o];
        sg[r][f * DOUTC + o] = fmaxf(v, 0.f);
    }
    __syncthreads();

    float s = sbo[o];
#pragma unroll
    for (int k = 0; k < FF * DOUTC; k++) s = fmaf(sg[r][k], sW[k * DOUTC + o], s);
    out[(size_t)gr * DOUTC + o] = s;
}

extern "C" void kernel_launch(void* const* d_in, const int* in_sizes, int n_in,
                              void* d_out, int out_size) {
    // metadata order: x, factor_embeddings, grid_embeddings, supports,
    //                 ln_gamma, ln_beta, W_gcn, b_gcn, W_out, b_out
    const float* x  = (const float*)d_in[0];
    const float* S  = (const float*)d_in[3];
    const float* Wg = (const float*)d_in[6];
    const float* bg = (const float*)d_in[7];
    const float* Wo = (const float*)d_in[8];
    const float* bo = (const float*)d_in[9];
    float* out = (float*)d_out;

    k_degpart<<<dim3(NF / 1024, ROWCH), 256>>>(S);
    k_finalize<<<NF / 256, 256>>>(S);
    k_hs<<<(NB * NF * DOUTC) / 256, 256>>>(x, Wg);
    k_gemm<<<dim3(NF / 128, KSPLIT), 256>>>(S);
    k_out<<<(NB * NN) / 8, 128>>>(Wo, bg, bo, out);
}

// round 9
// speedup vs baseline: 1.5216x; 1.5216x over previous
#include <cuda_runtime.h>
#include <cstdint>

// FactorGNN fused pipeline (dead attention branch removed).
//   A = supports, A[j,j] = (diag==0 ? 1 : diag)
//   deg[j] = sum_i A[i,j];  dinv = deg>0 ? rsqrt(deg) : 0
//   M[i,c] = dinv[i] * (x[b,i,:] @ W_gcn)      c = b*16+o  (64 cols)
//   C[j,c] = sum_i supports[i,j] * M[i,c]      (register-streamed GEMM, split-K=7)
//   g      = relu(dinv[j]*(C + corr[j]*M[j,c]) + b_gcn)
//   out    = g.reshape(.,160) @ W_out + b_out

#define NF     10240
#define NB     4
#define NN     1024
#define FF     10
#define DD     16
#define DOUTC  16
#define NCOL   64
#define ROWCH  40
#define KSPLIT 7
#define KCHUNK 1472          // multiple of 32; last chunk = 1408 (44 stages)

// Scratch (static device globals: allocation-free per harness rules)
__device__ float g_M[NF * NCOL];
__device__ float g_C[KSPLIT][NF * NCOL];
__device__ float g_degpart[ROWCH * NF];
__device__ float g_dinv[NF];
__device__ float g_corr[NF];

// ---- packed f32x2 helpers (sm_103a FFMA2 path) ----
__device__ __forceinline__ unsigned long long pk2(float lo, float hi) {
    unsigned long long r;
    asm("mov.b64 %0, {%1, %2};" : "=l"(r) : "f"(lo), "f"(hi));
    return r;
}
__device__ __forceinline__ void fma2(unsigned long long& d,
                                     unsigned long long a, unsigned long long b) {
    asm("fma.rn.f32x2 %0, %1, %2, %0;" : "+l"(d) : "l"(a), "l"(b));
}
__device__ __forceinline__ float2 upk2(unsigned long long v) {
    float2 f;
    asm("mov.b64 {%0, %1}, %2;" : "=f"(f.x), "=f"(f.y) : "l"(v));
    return f;
}

// ---- cp.async helpers ----
__device__ __forceinline__ void cpasync16(uint32_t saddr, const void* gptr) {
    asm volatile("cp.async.cg.shared.global [%0], [%1], 16;"
                 :: "r"(saddr), "l"(gptr));
}
__device__ __forceinline__ void cpasync_commit() {
    asm volatile("cp.async.commit_group;");
}
template <int N>
__device__ __forceinline__ void cpasync_wait() {
    asm volatile("cp.async.wait_group %0;" :: "n"(N));
}

// K1: partial column sums of supports (float4 lanes, HBM-bound)
__global__ void k_degpart(const float* __restrict__ S) {
    int j4 = blockIdx.x * 256 + threadIdx.x;
    int r0 = blockIdx.y * 256;
    const float4* p = (const float4*)S + (size_t)r0 * (NF / 4) + j4;
    float4 s = make_float4(0.f, 0.f, 0.f, 0.f);
#pragma unroll 8
    for (int r = 0; r < 256; r++) {
        float4 v = __ldcs(p + (size_t)r * (NF / 4));
        s.x += v.x; s.y += v.y; s.z += v.z; s.w += v.w;
    }
    ((float4*)g_degpart)[(size_t)blockIdx.y * (NF / 4) + j4] = s;
}

// K2: reduce partials, self-loop fix, produce dinv & corr
__global__ void k_finalize(const float* __restrict__ S) {
    int j = blockIdx.x * 256 + threadIdx.x;
    float s = 0.f;
#pragma unroll
    for (int p = 0; p < ROWCH; p++) s += g_degpart[p * NF + j];
    float diag = S[(size_t)j * NF + j];
    float corr = (diag == 0.f) ? 1.f : 0.f;
    float deg  = s + corr;
    g_dinv[j] = (deg > 0.f) ? rsqrtf(deg) : 0.f;
    g_corr[j] = corr;
}

// K3: M = dinv[i] * (x @ W_gcn), layout g_M[i*64 + b*16 + o]
__global__ void k_hs(const float* __restrict__ x, const float* __restrict__ Wg) {
    __shared__ float sW[DD * DOUTC];
    if (threadIdx.x < DD * DOUTC) sW[threadIdx.x] = Wg[threadIdx.x];
    __syncthreads();
    int g = blockIdx.x * 256 + threadIdx.x;
    int o = g & 15;
    int rest = g >> 4;
    int i = rest % NF;
    int b = rest / NF;
    const float* xr = x + ((size_t)b * NF + i) * DD;
    float h = 0.f;
#pragma unroll
    for (int d = 0; d < DD; d++) h = fmaf(xr[d], sW[d * DOUTC + o], h);
    g_M[i * NCOL + b * DOUTC + o] = g_dinv[i] * h;
}

// K4: C[ks][j,c] = sum_i S[i,j]*M[i,c].
// 256 thr: 64 j-groups x 4 c-groups (cg = tx>>6, uniform within warp -> broadcast LDS).
// Per thread: 4j x 16c = 32 FFMA2/iter.
// S: depth-4 register ring, unroll 4 (static indices), 1024-cyc latency cover.
// M: smem 32-row stages, double-buffered via cp.async.
__global__ __launch_bounds__(256, 2) void k_gemm(const float* __restrict__ S) {
    __shared__ alignas(16) float sM[2][32 * NCOL];

    const int tx = threadIdx.x;
    const int cg = tx >> 6;                 // 0..3, uniform within warp
    const int jt = tx & 63;                 // 0..63
    const int j  = blockIdx.x * 256 + jt * 4;
    const int c0 = cg * 16;
    const int ks = blockIdx.y;
    const int i0 = ks * KCHUNK;
    const int i1 = min(i0 + KCHUNK, NF);
    const int nst = (i1 - i0) >> 5;         // all chunks multiple of 32

    unsigned long long acc[4][8];
#pragma unroll
    for (int q = 0; q < 4; q++)
#pragma unroll
        for (int p = 0; p < 8; p++) acc[q][p] = 0ull;

    // S depth-4 register ring: rows i0..i0+3 preloaded
    const float4* Sbase = (const float4*)S + (j >> 2);
    float4 rs[4];
#pragma unroll
    for (int d = 0; d < 4; d++)
        rs[d] = __ldcs(Sbase + (size_t)(i0 + d) * (NF / 4));
    const float4* Spf = Sbase + (size_t)(i0 + 4) * (NF / 4);

    const float4* Mg = (const float4*)g_M;
    const uint32_t sa0 = (uint32_t)__cvta_generic_to_shared(&sM[0][0]);
    const uint32_t sa1 = (uint32_t)__cvta_generic_to_shared(&sM[1][0]);

    // prologue: stage 0 -> buf 0
    {
        const float4* src = Mg + (size_t)i0 * (NCOL / 4);
        cpasync16(sa0 + tx * 16, src + tx);
        cpasync16(sa0 + (tx + 256) * 16, src + tx + 256);
        cpasync_commit();
    }

    for (int t = 0; t < nst; ++t) {
        const int buf = t & 1;
        if (t + 1 < nst) {
            const uint32_t sa = buf ? sa0 : sa1;
            const float4* src = Mg + (size_t)(i0 + (t + 1) * 32) * (NCOL / 4);
            cpasync16(sa + tx * 16, src + tx);
            cpasync16(sa + (tx + 256) * 16, src + tx + 256);
            cpasync_commit();
            cpasync_wait<1>();                // stage t landed
        } else {
            cpasync_wait<0>();
        }
        __syncthreads();

        const int ibase = i0 + t * 32;
#pragma unroll 4
        for (int k = 0; k < 32; ++k) {
            float4 sv = rs[k & 3];
            rs[k & 3] = __ldcs(Spf);           // prefetch row ibase+k+4 (clamped)
            Spf += ((ibase + k + 5) < NF) ? (NF / 4) : 0;

            const float* mr = &sM[buf][k * NCOL + c0];
            ulonglong2 mA = *(const ulonglong2*)(mr);       // broadcast LDS.128
            ulonglong2 mB = *(const ulonglong2*)(mr + 4);
            ulonglong2 mC = *(const ulonglong2*)(mr + 8);
            ulonglong2 mD = *(const ulonglong2*)(mr + 12);
            unsigned long long b0 = mA.x, b1 = mA.y, b2 = mB.x, b3 = mB.y;
            unsigned long long b4 = mC.x, b5 = mC.y, b6 = mD.x, b7 = mD.y;

            unsigned long long a;
            a = pk2(sv.x, sv.x);
            fma2(acc[0][0], a, b0); fma2(acc[0][1], a, b1);
            fma2(acc[0][2], a, b2); fma2(acc[0][3], a, b3);
            fma2(acc[0][4], a, b4); fma2(acc[0][5], a, b5);
            fma2(acc[0][6], a, b6); fma2(acc[0][7], a, b7);
            a = pk2(sv.y, sv.y);
            fma2(acc[1][0], a, b0); fma2(acc[1][1], a, b1);
            fma2(acc[1][2], a, b2); fma2(acc[1][3], a, b3);
            fma2(acc[1][4], a, b4); fma2(acc[1][5], a, b5);
            fma2(acc[1][6], a, b6); fma2(acc[1][7], a, b7);
            a = pk2(sv.z, sv.z);
            fma2(acc[2][0], a, b0); fma2(acc[2][1], a, b1);
            fma2(acc[2][2], a, b2); fma2(acc[2][3], a, b3);
            fma2(acc[2][4], a, b4); fma2(acc[2][5], a, b5);
            fma2(acc[2][6], a, b6); fma2(acc[2][7], a, b7);
            a = pk2(sv.w, sv.w);
            fma2(acc[3][0], a, b0); fma2(acc[3][1], a, b1);
            fma2(acc[3][2], a, b2); fma2(acc[3][3], a, b3);
            fma2(acc[3][4], a, b4); fma2(acc[3][5], a, b5);
            fma2(acc[3][6], a, b6); fma2(acc[3][7], a, b7);
        }
        __syncthreads();                       // protect buf before overwrite
    }

    // write partials: rows j..j+3, cols c0..c0+15
#pragma unroll
    for (int q = 0; q < 4; q++) {
        float* Cp = g_C[ks] + (size_t)(j + q) * NCOL + c0;
        float2 v0 = upk2(acc[q][0]), v1 = upk2(acc[q][1]);
        float2 v2 = upk2(acc[q][2]), v3 = upk2(acc[q][3]);
        float2 v4 = upk2(acc[q][4]), v5 = upk2(acc[q][5]);
        float2 v6 = upk2(acc[q][6]), v7 = upk2(acc[q][7]);
        *(float4*)(Cp +  0) = make_float4(v0.x, v0.y, v1.x, v1.y);
        *(float4*)(Cp +  4) = make_float4(v2.x, v2.y, v3.x, v3.y);
        *(float4*)(Cp +  8) = make_float4(v4.x, v4.y, v5.x, v5.y);
        *(float4*)(Cp + 12) = make_float4(v6.x, v6.y, v7.x, v7.y);
    }
}

// K5: epilogue (sum split-K, diag corr, dinv[j], bias, relu) + output GEMM 160x16
__global__ void k_out(const float* __restrict__ Wout, const float* __restrict__ bgcn,
                      const float* __restrict__ bout, float* __restrict__ out) {
    __shared__ float sW[FF * DOUTC * DOUTC];
    __shared__ float sg[8][FF * DOUTC];
    __shared__ float sbg[DOUTC], sbo[DOUTC];
    const int tx = threadIdx.x;
    for (int i = tx; i < FF * DOUTC * DOUTC; i += 128) sW[i] = Wout[i];
    if (tx < DOUTC) { sbg[tx] = bgcn[tx]; sbo[tx] = bout[tx]; }
    __syncthreads();

    const int r = tx >> 4, o = tx & 15;
    const int gr = blockIdx.x * 8 + r;          // (b,n) flat, 0..4095
    const int b = gr >> 10, n = gr & 1023;

#pragma unroll
    for (int f = 0; f < FF; f++) {
        const int j = n * FF + f;
        const int cidx = j * NCOL + b * DOUTC + o;
        float v = 0.f;
#pragma unroll
        for (int s = 0; s < KSPLIT; s++) v += g_C[s][cidx];
        v += g_corr[j] * g_M[cidx];
        v = g_dinv[j] * v + sbg[o];
        sg[r][f * DOUTC + o] = fmaxf(v, 0.f);
    }
    __syncthreads();

    float s = sbo[o];
#pragma unroll
    for (int k = 0; k < FF * DOUTC; k++) s = fmaf(sg[r][k], sW[k * DOUTC + o], s);
    out[(size_t)gr * DOUTC + o] = s;
}

extern "C" void kernel_launch(void* const* d_in, const int* in_sizes, int n_in,
                              void* d_out, int out_size) {
    // metadata order: x, factor_embeddings, grid_embeddings, supports,
    //                 ln_gamma, ln_beta, W_gcn, b_gcn, W_out, b_out
    const float* x  = (const float*)d_in[0];
    const float* S  = (const float*)d_in[3];
    const float* Wg = (const float*)d_in[6];
    const float* bg = (const float*)d_in[7];
    const float* Wo = (const float*)d_in[8];
    const float* bo = (const float*)d_in[9];
    float* out = (float*)d_out;

    k_degpart<<<dim3(NF / 1024, ROWCH), 256>>>(S);
    k_finalize<<<NF / 256, 256>>>(S);
    k_hs<<<(NB * NF * DOUTC) / 256, 256>>>(x, Wg);
    k_gemm<<<dim3(NF / 256, KSPLIT), 256>>>(S);
    k_out<<<(NB * NN) / 8, 128>>>(Wo, bg, bo, out);
}